// round 2
// baseline (speedup 1.0000x reference)
#include <cuda_runtime.h>
#include <cuda_bf16.h>

// Problem constants
#define NB    4096
#define LATD  64
#define GDIM  2016

// Scratch for gi = gi_latent @ W_up^T + b_up   (33 MB)
__device__ float g_gi[NB * GDIM];

// ---------------------------------------------------------------------------
// packed f32x2 helpers (sm_100+)
// ---------------------------------------------------------------------------
__device__ __forceinline__ unsigned long long pack2(float x) {
    unsigned long long r;
    asm("mov.b64 %0, {%1, %1};" : "=l"(r) : "f"(x));
    return r;
}
__device__ __forceinline__ void fma2(unsigned long long& acc, unsigned long long a, unsigned long long b) {
    asm("fma.rn.f32x2 %0, %1, %2, %0;" : "+l"(acc) : "l"(a), "l"(b));
}
__device__ __forceinline__ float2 unpack2(unsigned long long v) {
    float2 f;
    asm("mov.b64 {%0, %1}, %2;" : "=f"(f.x), "=f"(f.y) : "l"(v));
    return f;
}

// ---------------------------------------------------------------------------
// Kernel 1: gi = gi_latent @ W_up^T + b_up
// tile: 64 samples x 64 gd-cols, 256 threads, 4x4 register tile per thread
// ---------------------------------------------------------------------------
__global__ __launch_bounds__(256) void k_up(const float* __restrict__ gi_latent,
                                            const float* __restrict__ W_up,
                                            const float* __restrict__ b_up) {
    __shared__ float sA[64 * 64];  // samples x k
    __shared__ float sW[64 * 64];  // gd x k
    const int s0 = blockIdx.y * 64;
    const int g0 = blockIdx.x * 64;
    const int t  = threadIdx.x;

    // load A tile (full: sample dim is always in range)
    const float4* Ag = reinterpret_cast<const float4*>(gi_latent + s0 * 64);
#pragma unroll
    for (int q = 0; q < 4; q++) {
        int e = t + q * 256;                 // float4 index, 1024 total
        reinterpret_cast<float4*>(sA)[e] = Ag[e];
    }
    // load W tile (guard rows beyond GDIM)
#pragma unroll
    for (int q = 0; q < 4; q++) {
        int e   = t + q * 256;
        int row = e >> 4;
        int c4  = e & 15;
        int g   = g0 + row;
        float4 v = make_float4(0.f, 0.f, 0.f, 0.f);
        if (g < GDIM) v = reinterpret_cast<const float4*>(W_up + g * 64)[c4];
        reinterpret_cast<float4*>(sW)[e] = v;
    }
    __syncthreads();

    const int tx4 = (t & 15) * 4;
    const int ty4 = (t >> 4) * 4;
    float acc[4][4];
#pragma unroll
    for (int r = 0; r < 4; r++)
#pragma unroll
        for (int c = 0; c < 4; c++) acc[r][c] = 0.f;

#pragma unroll 8
    for (int k = 0; k < 64; k++) {
        float xv[4], wv[4];
#pragma unroll
        for (int r = 0; r < 4; r++) xv[r] = sA[(ty4 + r) * 64 + k];
#pragma unroll
        for (int c = 0; c < 4; c++) wv[c] = sW[(tx4 + c) * 64 + k];
#pragma unroll
        for (int r = 0; r < 4; r++)
#pragma unroll
            for (int c = 0; c < 4; c++) acc[r][c] += xv[r] * wv[c];
    }

#pragma unroll
    for (int r = 0; r < 4; r++)
#pragma unroll
        for (int c = 0; c < 4; c++) {
            int g = g0 + tx4 + c;
            if (g < GDIM) g_gi[(size_t)(s0 + ty4 + r) * GDIM + g] = acc[r][c] + b_up[g];
        }
}

// ---------------------------------------------------------------------------
// 64x64x64 matmul step on smem:  OUT = s*(X @ Y) + a*X   (barrier-protected)
// 256 threads, 4x4 tile per thread, packed f32x2 FMAs.
// OUT may alias X, Y, or both (writes happen after a full barrier).
// ---------------------------------------------------------------------------
__device__ __noinline__ void mm_step(const float* X, const float* Y, float* OUT,
                                     float a, float s) {
    const int t   = threadIdx.x;
    const int tx4 = (t & 15) * 4;
    const int ty4 = (t >> 4) * 4;

    unsigned long long acc[4][2];
#pragma unroll
    for (int r = 0; r < 4; r++) { acc[r][0] = 0ull; acc[r][1] = 0ull; }

    const float* Xp = X + ty4 * 64;
    const float* Yp = Y + tx4;

#pragma unroll 16
    for (int k = 0; k < 64; k++) {
        ulonglong2 y = *reinterpret_cast<const ulonglong2*>(Yp + k * 64);
#pragma unroll
        for (int r = 0; r < 4; r++) {
            unsigned long long xx = pack2(Xp[r * 64 + k]);
            fma2(acc[r][0], xx, y.x);
            fma2(acc[r][1], xx, y.y);
        }
    }

    // epilogue: res = s*acc + a*X[i][j]
    float res[4][4];
#pragma unroll
    for (int r = 0; r < 4; r++) {
        float2 lo = unpack2(acc[r][0]);
        float2 hi = unpack2(acc[r][1]);
        const float* xr = X + (ty4 + r) * 64 + tx4;
        res[r][0] = s * lo.x + a * xr[0];
        res[r][1] = s * lo.y + a * xr[1];
        res[r][2] = s * hi.x + a * xr[2];
        res[r][3] = s * hi.y + a * xr[3];
    }
    __syncthreads();
#pragma unroll
    for (int r = 0; r < 4; r++)
        *reinterpret_cast<float4*>(OUT + (ty4 + r) * 64 + tx4) =
            make_float4(res[r][0], res[r][1], res[r][2], res[r][3]);
    __syncthreads();
}

// ---------------------------------------------------------------------------
// Kernel 2: per-sample Cayley map (Newton-Schulz) + MLP tail, fully fused.
// grid = 4096 CTAs (1 sample each), 256 threads.
// dynamic smem: B, Z, P, U (4 x 64x64 f32) + small vectors.
// ---------------------------------------------------------------------------
__global__ __launch_bounds__(256) void k_main(
    const float* __restrict__ li_latent,
    const float* __restrict__ W1, const float* __restrict__ b1,
    const float* __restrict__ W2, const float* __restrict__ b2,
    const float* __restrict__ W3, const float* __restrict__ b3,
    const float* __restrict__ W4, const float* __restrict__ b4,
    const float* __restrict__ W5, const float* __restrict__ b5,
    const float* __restrict__ W6, const float* __restrict__ b6,
    float* __restrict__ out) {
    extern __shared__ float smem[];
    float* sB   = smem;               // 4096
    float* sZ   = smem + 4096;        // 4096
    float* sP   = smem + 8192;        // 4096
    float* sU   = smem + 12288;       // 4096
    float* sv   = smem + 16384;       // 256 small vectors
    float* sred = smem + 16384 + 256; // 32 reduction scratch

    const int n = blockIdx.x;
    const int t = threadIdx.x;
    const float* gi = g_gi + (size_t)n * GDIM;

    // ---- build B = I - (A^T - A), A lower-tri from gi ----
    for (int e = t; e < GDIM; e += 256) {
        int i = (int)((1.0f + sqrtf(1.0f + 8.0f * (float)e)) * 0.5f);
        while (i * (i - 1) / 2 > e) i--;
        while ((i + 1) * i / 2 <= e) i++;
        int j   = e - i * (i - 1) / 2;
        float v = gi[e];
        sB[i * 64 + j] = v;    // i > j
        sB[j * 64 + i] = -v;
    }
    if (t < 64) sB[t * 65] = 1.0f;
    __syncthreads();

    // ---- norms = sum(|B|) * max(|B|), Z0 = B^T / norms ----
    float lsum = 0.f, lmax = 0.f;
#pragma unroll
    for (int q = 0; q < 16; q++) {
        float v = fabsf(sB[t * 16 + q]);
        lsum += v;
        lmax = fmaxf(lmax, v);
    }
#pragma unroll
    for (int o = 16; o; o >>= 1) {
        lsum += __shfl_xor_sync(0xFFFFFFFFu, lsum, o);
        lmax = fmaxf(lmax, __shfl_xor_sync(0xFFFFFFFFu, lmax, o));
    }
    if ((t & 31) == 0) { sred[t >> 5] = lsum; sred[8 + (t >> 5)] = lmax; }
    __syncthreads();
    if (t == 0) {
        float S = 0.f, M = 0.f;
        for (int w = 0; w < 8; w++) { S += sred[w]; M = fmaxf(M, sred[8 + w]); }
        sred[16] = 1.0f / (S * M);
    }
    __syncthreads();
    const float invn = sred[16];
#pragma unroll
    for (int q = 0; q < 16; q++) {
        int e = t * 16 + q;
        int i = e >> 6, j = e & 63;
        sZ[e] = sB[j * 64 + i] * invn;
    }
    __syncthreads();

    // ---- 10 Newton-Schulz iterations ----
    // Z = 0.25 * Z @ (13I - BZ@(15I - BZ@(7I - BZ)))
#pragma unroll 1
    for (int it = 0; it < 10; it++) {
        mm_step(sB, sZ, sP, 0.0f, 1.0f);     // P  = B@Z
        mm_step(sP, sP, sU, 7.0f, -1.0f);    // U  = 7P - P@P        (= BZ@(7I-BZ))
        mm_step(sP, sU, sU, 15.0f, -1.0f);   // U  = 15P - P@U       (= BZ@(15I-...))
        mm_step(sZ, sU, sZ, 3.25f, -0.25f);  // Z  = 0.25*(13Z - Z@U)
    }
    // R = Z @ Q = Z @ (2I - B) = 2Z - Z@B   -> stored in sP
    mm_step(sZ, sB, sP, 2.0f, -1.0f);
    const float* R = sP;

    // ---- MLP tail ----
    if (t < 64) sv[t] = li_latent[n * 64 + t];
    __syncthreads();

    // mis[j] = sum_i R[i][j] * li[i]
    if (t < 64) {
        float acc = 0.f;
        for (int i = 0; i < 64; i++) acc += R[i * 64 + t] * sv[i];
        sv[64 + t] = acc;
    }
    __syncthreads();
    // h = relu(mis @ W1^T + b1)
    if (t < 64) {
        float acc = b1[t];
        const float* w = W1 + t * 64;
        for (int k = 0; k < 64; k++) acc += sv[64 + k] * w[k];
        sv[128 + t] = fmaxf(acc, 0.f);
    }
    __syncthreads();
    // fc2 = h @ W2^T + b2
    if (t < 64) {
        float acc = b2[t];
        const float* w = W2 + t * 64;
        for (int k = 0; k < 64; k++) acc += sv[128 + k] * w[k];
        sv[192 + t] = acc;
    }
    __syncthreads();
    // latent[i] = sum_j R[i][j] * fc2[j]   (skewed j to dodge bank conflicts)
    if (t < 64) {
        float acc = 0.f;
        for (int jj = 0; jj < 64; jj++) {
            int j = (t + jj) & 63;
            acc += R[t * 64 + j] * sv[192 + j];
        }
        sv[64 + t] = acc;                       // latent (overwrites mis)
        out[262144 + 8192 + n * 64 + t] = acc;  // latent output
    }
    __syncthreads();
    // t3 = relu(latent @ W3^T + b3)
    if (t < 64) {
        float acc = b3[t];
        const float* w = W3 + t * 64;
        for (int k = 0; k < 64; k++) acc += sv[64 + k] * w[k];
        sv[128 + t] = fmaxf(acc, 0.f);
    }
    __syncthreads();
    // recons = t3 @ W4^T + b4 ; t5 = relu(latent @ W5^T + b5)
    if (t < 64) {
        float acc = b4[t];
        const float* w = W4 + t * 64;
        for (int j = 0; j < 64; j++) acc += sv[128 + j] * w[j];
        out[n * 64 + t] = acc;                  // recons output

        float acc5 = b5[t];
        const float* w5 = W5 + t * 64;
        for (int k = 0; k < 64; k++) acc5 += sv[64 + k] * w5[k];
        sv[192 + t] = fmaxf(acc5, 0.f);         // t5 (overwrites fc2)
    }
    __syncthreads();
    // pred = t5 @ W6^T + b6   (2 outputs)
    if (t < 2) {
        float acc = b6[t];
        const float* w = W6 + t * 64;
        for (int j = 0; j < 64; j++) acc += sv[192 + j] * w[j];
        out[262144 + n * 2 + t] = acc;          // pred output
    }
}

// ---------------------------------------------------------------------------
// launch
// ---------------------------------------------------------------------------
#define MAIN_SMEM_BYTES ((4 * 4096 + 256 + 32) * sizeof(float))

extern "C" void kernel_launch(void* const* d_in, const int* in_sizes, int n_in,
                              void* d_out, int out_size) {
    const float* li    = (const float*)d_in[0];
    const float* gl    = (const float*)d_in[1];
    const float* W_up  = (const float*)d_in[2];
    const float* b_up  = (const float*)d_in[3];
    const float* W1    = (const float*)d_in[4];
    const float* b1    = (const float*)d_in[5];
    const float* W2    = (const float*)d_in[6];
    const float* b2    = (const float*)d_in[7];
    const float* W3    = (const float*)d_in[8];
    const float* b3    = (const float*)d_in[9];
    const float* W4    = (const float*)d_in[10];
    const float* b4    = (const float*)d_in[11];
    const float* W5    = (const float*)d_in[12];
    const float* b5    = (const float*)d_in[13];
    const float* W6    = (const float*)d_in[14];
    const float* b6    = (const float*)d_in[15];
    float* out = (float*)d_out;

    cudaFuncSetAttribute(k_main, cudaFuncAttributeMaxDynamicSharedMemorySize,
                         (int)MAIN_SMEM_BYTES);

    k_up<<<dim3((GDIM + 63) / 64, NB / 64), 256>>>(gl, W_up, b_up);
    k_main<<<NB, 256, MAIN_SMEM_BYTES>>>(li, W1, b1, W2, b2, W3, b3, W4, b4,
                                         W5, b5, W6, b6, out);
}

// round 3
// speedup vs baseline: 1.0035x; 1.0035x over previous
#include <cuda_runtime.h>
#include <cuda_bf16.h>

// Problem constants
#define NB    4096
#define LATD  64
#define GDIM  2016

// Scratch for gi = gi_latent @ W_up^T + b_up   (33 MB)
__device__ float g_gi[NB * GDIM];

// ---------------------------------------------------------------------------
// packed f32x2 helpers (sm_100+)
// ---------------------------------------------------------------------------
__device__ __forceinline__ unsigned long long pack2(float x) {
    unsigned long long r;
    asm("mov.b64 %0, {%1, %1};" : "=l"(r) : "f"(x));
    return r;
}
__device__ __forceinline__ void fma2(unsigned long long& acc, unsigned long long a, unsigned long long b) {
    asm("fma.rn.f32x2 %0, %1, %2, %0;" : "+l"(acc) : "l"(a), "l"(b));
}
__device__ __forceinline__ float2 unpack2(unsigned long long v) {
    float2 f;
    asm("mov.b64 {%0, %1}, %2;" : "=f"(f.x), "=f"(f.y) : "l"(v));
    return f;
}

// ---------------------------------------------------------------------------
// Kernel 1: gi = gi_latent @ W_up^T + b_up
// tile: 64 samples x 64 gd-cols, 256 threads, 4x4 register tile per thread
// ---------------------------------------------------------------------------
__global__ __launch_bounds__(256) void k_up(const float* __restrict__ gi_latent,
                                            const float* __restrict__ W_up,
                                            const float* __restrict__ b_up) {
    __shared__ float sA[64 * 64];  // samples x k
    __shared__ float sW[64 * 64];  // gd x k
    const int s0 = blockIdx.y * 64;
    const int g0 = blockIdx.x * 64;
    const int t  = threadIdx.x;

    const float4* Ag = reinterpret_cast<const float4*>(gi_latent + s0 * 64);
#pragma unroll
    for (int q = 0; q < 4; q++) {
        int e = t + q * 256;
        reinterpret_cast<float4*>(sA)[e] = Ag[e];
    }
#pragma unroll
    for (int q = 0; q < 4; q++) {
        int e   = t + q * 256;
        int row = e >> 4;
        int c4  = e & 15;
        int g   = g0 + row;
        float4 v = make_float4(0.f, 0.f, 0.f, 0.f);
        if (g < GDIM) v = reinterpret_cast<const float4*>(W_up + g * 64)[c4];
        reinterpret_cast<float4*>(sW)[e] = v;
    }
    __syncthreads();

    const int tx4 = (t & 15) * 4;
    const int ty4 = (t >> 4) * 4;
    float acc[4][4];
#pragma unroll
    for (int r = 0; r < 4; r++)
#pragma unroll
        for (int c = 0; c < 4; c++) acc[r][c] = 0.f;

#pragma unroll 8
    for (int k = 0; k < 64; k++) {
        float xv[4], wv[4];
#pragma unroll
        for (int r = 0; r < 4; r++) xv[r] = sA[(ty4 + r) * 64 + k];
#pragma unroll
        for (int c = 0; c < 4; c++) wv[c] = sW[(tx4 + c) * 64 + k];
#pragma unroll
        for (int r = 0; r < 4; r++)
#pragma unroll
            for (int c = 0; c < 4; c++) acc[r][c] += xv[r] * wv[c];
    }

#pragma unroll
    for (int r = 0; r < 4; r++)
#pragma unroll
        for (int c = 0; c < 4; c++) {
            int g = g0 + tx4 + c;
            if (g < GDIM) g_gi[(size_t)(s0 + ty4 + r) * GDIM + g] = acc[r][c] + b_up[g];
        }
}

// ---------------------------------------------------------------------------
// 64x64x64 matmul step on smem:  OUT = s*(X @ Y) + a*X   (barrier-protected)
// 256 threads, 4x4 tile per thread, packed f32x2 FMAs.
// X loads are vectorized ALONG K (one LDS.128 per row per 4 k-steps) so the
// smem wavefront cost is 3/warp/k (1 for X, 2 for the 256B Y row) instead of
// 6 -> crossbar drops below the FFMA2 issue floor.
// OUT may alias X, Y, or both (writes happen after a full barrier).
// ---------------------------------------------------------------------------
__device__ __noinline__ void mm_step(const float* X, const float* Y, float* OUT,
                                     float a, float s) {
    const int t   = threadIdx.x;
    const int tx4 = (t & 15) * 4;
    const int ty4 = (t >> 4) * 4;

    unsigned long long acc[4][2];
#pragma unroll
    for (int r = 0; r < 4; r++) { acc[r][0] = 0ull; acc[r][1] = 0ull; }

    const float* Xp = X + ty4 * 64;
    const float* Yp = Y + tx4;

#pragma unroll 8
    for (int k4 = 0; k4 < 16; k4++) {
        float4 xv[4];
#pragma unroll
        for (int r = 0; r < 4; r++)
            xv[r] = *reinterpret_cast<const float4*>(Xp + r * 64 + k4 * 4);
#pragma unroll
        for (int kk = 0; kk < 4; kk++) {
            ulonglong2 y = *reinterpret_cast<const ulonglong2*>(Yp + (k4 * 4 + kk) * 64);
#pragma unroll
            for (int r = 0; r < 4; r++) {
                unsigned long long xx = pack2(reinterpret_cast<const float*>(&xv[r])[kk]);
                fma2(acc[r][0], xx, y.x);
                fma2(acc[r][1], xx, y.y);
            }
        }
    }

    // epilogue: res = s*acc + a*X[i][j]
    float res[4][4];
#pragma unroll
    for (int r = 0; r < 4; r++) {
        float2 lo = unpack2(acc[r][0]);
        float2 hi = unpack2(acc[r][1]);
        float4 xr = *reinterpret_cast<const float4*>(X + (ty4 + r) * 64 + tx4);
        res[r][0] = s * lo.x + a * xr.x;
        res[r][1] = s * lo.y + a * xr.y;
        res[r][2] = s * hi.x + a * xr.z;
        res[r][3] = s * hi.y + a * xr.w;
    }
    __syncthreads();
#pragma unroll
    for (int r = 0; r < 4; r++)
        *reinterpret_cast<float4*>(OUT + (ty4 + r) * 64 + tx4) =
            make_float4(res[r][0], res[r][1], res[r][2], res[r][3]);
    __syncthreads();
}

// ---------------------------------------------------------------------------
// Kernel 2: per-sample Cayley map (Newton-Schulz) + MLP tail, fully fused.
// grid = 4096 CTAs (1 sample each), 256 threads.
// dynamic smem: B, Z, P, U (4 x 64x64 f32) + small vectors.
// ---------------------------------------------------------------------------
__global__ __launch_bounds__(256) void k_main(
    const float* __restrict__ li_latent,
    const float* __restrict__ W1, const float* __restrict__ b1,
    const float* __restrict__ W2, const float* __restrict__ b2,
    const float* __restrict__ W3, const float* __restrict__ b3,
    const float* __restrict__ W4, const float* __restrict__ b4,
    const float* __restrict__ W5, const float* __restrict__ b5,
    const float* __restrict__ W6, const float* __restrict__ b6,
    float* __restrict__ out) {
    extern __shared__ float smem[];
    float* sB   = smem;               // 4096
    float* sZ   = smem + 4096;        // 4096
    float* sP   = smem + 8192;        // 4096
    float* sU   = smem + 12288;       // 4096
    float* sv   = smem + 16384;       // 256 small vectors
    float* sred = smem + 16384 + 256; // 32 reduction scratch

    const int n = blockIdx.x;
    const int t = threadIdx.x;
    const float* gi = g_gi + (size_t)n * GDIM;

    // ---- build B = I - (A^T - A), A lower-tri from gi ----
    for (int e = t; e < GDIM; e += 256) {
        int i = (int)((1.0f + sqrtf(1.0f + 8.0f * (float)e)) * 0.5f);
        while (i * (i - 1) / 2 > e) i--;
        while ((i + 1) * i / 2 <= e) i++;
        int j   = e - i * (i - 1) / 2;
        float v = gi[e];
        sB[i * 64 + j] = v;    // i > j
        sB[j * 64 + i] = -v;
    }
    if (t < 64) sB[t * 65] = 1.0f;
    __syncthreads();

    // ---- norms = sum(|B|) * max(|B|), Z0 = B^T / norms ----
    float lsum = 0.f, lmax = 0.f;
#pragma unroll
    for (int q = 0; q < 16; q++) {
        float v = fabsf(sB[t * 16 + q]);
        lsum += v;
        lmax = fmaxf(lmax, v);
    }
#pragma unroll
    for (int o = 16; o; o >>= 1) {
        lsum += __shfl_xor_sync(0xFFFFFFFFu, lsum, o);
        lmax = fmaxf(lmax, __shfl_xor_sync(0xFFFFFFFFu, lmax, o));
    }
    if ((t & 31) == 0) { sred[t >> 5] = lsum; sred[8 + (t >> 5)] = lmax; }
    __syncthreads();
    if (t == 0) {
        float S = 0.f, M = 0.f;
        for (int w = 0; w < 8; w++) { S += sred[w]; M = fmaxf(M, sred[8 + w]); }
        sred[16] = 1.0f / (S * M);
    }
    __syncthreads();
    const float invn = sred[16];
#pragma unroll
    for (int q = 0; q < 16; q++) {
        int e = t * 16 + q;
        int i = e >> 6, j = e & 63;
        sZ[e] = sB[j * 64 + i] * invn;
    }
    __syncthreads();

    // ---- 10 Newton-Schulz iterations ----
    // Z = 0.25 * Z @ (13I - BZ@(15I - BZ@(7I - BZ)))
#pragma unroll 1
    for (int it = 0; it < 10; it++) {
        mm_step(sB, sZ, sP, 0.0f, 1.0f);     // P  = B@Z
        mm_step(sP, sP, sU, 7.0f, -1.0f);    // U  = 7P - P@P        (= BZ@(7I-BZ))
        mm_step(sP, sU, sU, 15.0f, -1.0f);   // U  = 15P - P@U       (= BZ@(15I-...))
        mm_step(sZ, sU, sZ, 3.25f, -0.25f);  // Z  = 0.25*(13Z - Z@U)
    }
    // R = Z @ Q = Z @ (2I - B) = 2Z - Z@B   -> stored in sP
    mm_step(sZ, sB, sP, 2.0f, -1.0f);
    const float* R = sP;

    // ---- MLP tail ----
    if (t < 64) sv[t] = li_latent[n * 64 + t];
    __syncthreads();

    // mis[j] = sum_i R[i][j] * li[i]
    if (t < 64) {
        float acc = 0.f;
        for (int i = 0; i < 64; i++) acc += R[i * 64 + t] * sv[i];
        sv[64 + t] = acc;
    }
    __syncthreads();
    // h = relu(mis @ W1^T + b1)
    if (t < 64) {
        float acc = b1[t];
        const float* w = W1 + t * 64;
        for (int k = 0; k < 64; k++) acc += sv[64 + k] * w[k];
        sv[128 + t] = fmaxf(acc, 0.f);
    }
    __syncthreads();
    // fc2 = h @ W2^T + b2
    if (t < 64) {
        float acc = b2[t];
        const float* w = W2 + t * 64;
        for (int k = 0; k < 64; k++) acc += sv[128 + k] * w[k];
        sv[192 + t] = acc;
    }
    __syncthreads();
    // latent[i] = sum_j R[i][j] * fc2[j]   (skewed j to dodge bank conflicts)
    if (t < 64) {
        float acc = 0.f;
        for (int jj = 0; jj < 64; jj++) {
            int j = (t + jj) & 63;
            acc += R[t * 64 + j] * sv[192 + j];
        }
        sv[64 + t] = acc;                       // latent (overwrites mis)
        out[262144 + 8192 + n * 64 + t] = acc;  // latent output
    }
    __syncthreads();
    // t3 = relu(latent @ W3^T + b3)
    if (t < 64) {
        float acc = b3[t];
        const float* w = W3 + t * 64;
        for (int k = 0; k < 64; k++) acc += sv[64 + k] * w[k];
        sv[128 + t] = fmaxf(acc, 0.f);
    }
    __syncthreads();
    // recons = t3 @ W4^T + b4 ; t5 = relu(latent @ W5^T + b5)
    if (t < 64) {
        float acc = b4[t];
        const float* w = W4 + t * 64;
        for (int j = 0; j < 64; j++) acc += sv[128 + j] * w[j];
        out[n * 64 + t] = acc;                  // recons output

        float acc5 = b5[t];
        const float* w5 = W5 + t * 64;
        for (int k = 0; k < 64; k++) acc5 += sv[64 + k] * w5[k];
        sv[192 + t] = fmaxf(acc5, 0.f);         // t5 (overwrites fc2)
    }
    __syncthreads();
    // pred = t5 @ W6^T + b6   (2 outputs)
    if (t < 2) {
        float acc = b6[t];
        const float* w = W6 + t * 64;
        for (int j = 0; j < 64; j++) acc += sv[192 + j] * w[j];
        out[262144 + n * 2 + t] = acc;          // pred output
    }
}

// ---------------------------------------------------------------------------
// launch
// ---------------------------------------------------------------------------
#define MAIN_SMEM_BYTES ((4 * 4096 + 256 + 32) * sizeof(float))

extern "C" void kernel_launch(void* const* d_in, const int* in_sizes, int n_in,
                              void* d_out, int out_size) {
    const float* li    = (const float*)d_in[0];
    const float* gl    = (const float*)d_in[1];
    const float* W_up  = (const float*)d_in[2];
    const float* b_up  = (const float*)d_in[3];
    const float* W1    = (const float*)d_in[4];
    const float* b1    = (const float*)d_in[5];
    const float* W2    = (const float*)d_in[6];
    const float* b2    = (const float*)d_in[7];
    const float* W3    = (const float*)d_in[8];
    const float* b3    = (const float*)d_in[9];
    const float* W4    = (const float*)d_in[10];
    const float* b4    = (const float*)d_in[11];
    const float* W5    = (const float*)d_in[12];
    const float* b5    = (const float*)d_in[13];
    const float* W6    = (const float*)d_in[14];
    const float* b6    = (const float*)d_in[15];
    float* out = (float*)d_out;

    cudaFuncSetAttribute(k_main, cudaFuncAttributeMaxDynamicSharedMemorySize,
                         (int)MAIN_SMEM_BYTES);

    k_up<<<dim3((GDIM + 63) / 64, NB / 64), 256>>>(gl, W_up, b_up);
    k_main<<<NB, 256, MAIN_SMEM_BYTES>>>(li, W1, b1, W2, b2, W3, b3, W4, b4,
                                         W5, b5, W6, b6, out);
}

// round 4
// speedup vs baseline: 1.0054x; 1.0019x over previous
#include <cuda_runtime.h>
#include <cuda_bf16.h>

// Problem constants
#define NB    4096
#define LATD  64
#define GDIM  2016

// Scratch for gi = gi_latent @ W_up^T + b_up   (33 MB)
__device__ float g_gi[NB * GDIM];

// ---------------------------------------------------------------------------
// packed f32x2 helpers (sm_100+)
// ---------------------------------------------------------------------------
__device__ __forceinline__ unsigned long long pack2(float x) {
    unsigned long long r;
    asm("mov.b64 %0, {%1, %1};" : "=l"(r) : "f"(x));
    return r;
}
__device__ __forceinline__ void fma2(unsigned long long& acc, unsigned long long a, unsigned long long b) {
    asm("fma.rn.f32x2 %0, %1, %2, %0;" : "+l"(acc) : "l"(a), "l"(b));
}
__device__ __forceinline__ float2 unpack2(unsigned long long v) {
    float2 f;
    asm("mov.b64 {%0, %1}, %2;" : "=f"(f.x), "=f"(f.y) : "l"(v));
    return f;
}

// ---------------------------------------------------------------------------
// Kernel 1: gi = gi_latent @ W_up^T + b_up
// tile: 64 samples x 64 gd-cols, 256 threads, 4x4 register tile per thread
// ---------------------------------------------------------------------------
__global__ __launch_bounds__(256) void k_up(const float* __restrict__ gi_latent,
                                            const float* __restrict__ W_up,
                                            const float* __restrict__ b_up) {
    __shared__ float sA[64 * 64];  // samples x k
    __shared__ float sW[64 * 64];  // gd x k
    const int s0 = blockIdx.y * 64;
    const int g0 = blockIdx.x * 64;
    const int t  = threadIdx.x;

    const float4* Ag = reinterpret_cast<const float4*>(gi_latent + s0 * 64);
#pragma unroll
    for (int q = 0; q < 4; q++) {
        int e = t + q * 256;
        reinterpret_cast<float4*>(sA)[e] = Ag[e];
    }
#pragma unroll
    for (int q = 0; q < 4; q++) {
        int e   = t + q * 256;
        int row = e >> 4;
        int c4  = e & 15;
        int g   = g0 + row;
        float4 v = make_float4(0.f, 0.f, 0.f, 0.f);
        if (g < GDIM) v = reinterpret_cast<const float4*>(W_up + g * 64)[c4];
        reinterpret_cast<float4*>(sW)[e] = v;
    }
    __syncthreads();

    const int tx4 = (t & 15) * 4;
    const int ty4 = (t >> 4) * 4;
    float acc[4][4];
#pragma unroll
    for (int r = 0; r < 4; r++)
#pragma unroll
        for (int c = 0; c < 4; c++) acc[r][c] = 0.f;

#pragma unroll 8
    for (int k = 0; k < 64; k++) {
        float xv[4], wv[4];
#pragma unroll
        for (int r = 0; r < 4; r++) xv[r] = sA[(ty4 + r) * 64 + k];
#pragma unroll
        for (int c = 0; c < 4; c++) wv[c] = sW[(tx4 + c) * 64 + k];
#pragma unroll
        for (int r = 0; r < 4; r++)
#pragma unroll
            for (int c = 0; c < 4; c++) acc[r][c] += xv[r] * wv[c];
    }

#pragma unroll
    for (int r = 0; r < 4; r++)
#pragma unroll
        for (int c = 0; c < 4; c++) {
            int g = g0 + tx4 + c;
            if (g < GDIM) g_gi[(size_t)(s0 + ty4 + r) * GDIM + g] = acc[r][c] + b_up[g];
        }
}

// ---------------------------------------------------------------------------
// 64x64x64 matmul step on smem:  OUT = s*(X @ Y) + a*X   (barrier-protected)
// 256 threads, 4x4 tile per thread, packed f32x2 FMAs.
// X loads are vectorized ALONG K (one LDS.128 per row per 4 k-steps) so the
// smem wavefront cost is 3/warp/k (1 for X, 2 for the 256B Y row) instead of
// 6 -> crossbar drops below the FFMA2 issue floor.
// OUT may alias X, Y, or both (writes happen after a full barrier).
// ---------------------------------------------------------------------------
__device__ __noinline__ void mm_step(const float* X, const float* Y, float* OUT,
                                     float a, float s) {
    const int t   = threadIdx.x;
    const int tx4 = (t & 15) * 4;
    const int ty4 = (t >> 4) * 4;

    unsigned long long acc[4][2];
#pragma unroll
    for (int r = 0; r < 4; r++) { acc[r][0] = 0ull; acc[r][1] = 0ull; }

    const float* Xp = X + ty4 * 64;
    const float* Yp = Y + tx4;

#pragma unroll 8
    for (int k4 = 0; k4 < 16; k4++) {
        float4 xv[4];
#pragma unroll
        for (int r = 0; r < 4; r++)
            xv[r] = *reinterpret_cast<const float4*>(Xp + r * 64 + k4 * 4);
#pragma unroll
        for (int kk = 0; kk < 4; kk++) {
            ulonglong2 y = *reinterpret_cast<const ulonglong2*>(Yp + (k4 * 4 + kk) * 64);
#pragma unroll
            for (int r = 0; r < 4; r++) {
                unsigned long long xx = pack2(reinterpret_cast<const float*>(&xv[r])[kk]);
                fma2(acc[r][0], xx, y.x);
                fma2(acc[r][1], xx, y.y);
            }
        }
    }

    // epilogue: res = s*acc + a*X[i][j]
    float res[4][4];
#pragma unroll
    for (int r = 0; r < 4; r++) {
        float2 lo = unpack2(acc[r][0]);
        float2 hi = unpack2(acc[r][1]);
        float4 xr = *reinterpret_cast<const float4*>(X + (ty4 + r) * 64 + tx4);
        res[r][0] = s * lo.x + a * xr.x;
        res[r][1] = s * lo.y + a * xr.y;
        res[r][2] = s * hi.x + a * xr.z;
        res[r][3] = s * hi.y + a * xr.w;
    }
    __syncthreads();
#pragma unroll
    for (int r = 0; r < 4; r++)
        *reinterpret_cast<float4*>(OUT + (ty4 + r) * 64 + tx4) =
            make_float4(res[r][0], res[r][1], res[r][2], res[r][3]);
    __syncthreads();
}

// ---------------------------------------------------------------------------
// Kernel 2: per-sample Cayley map (Newton-Schulz) + MLP tail, fully fused.
// grid = 4096 CTAs (1 sample each), 256 threads.
// dynamic smem: B, Z, P, U (4 x 64x64 f32) + small vectors.
// ---------------------------------------------------------------------------
__global__ __launch_bounds__(256) void k_main(
    const float* __restrict__ li_latent,
    const float* __restrict__ W1, const float* __restrict__ b1,
    const float* __restrict__ W2, const float* __restrict__ b2,
    const float* __restrict__ W3, const float* __restrict__ b3,
    const float* __restrict__ W4, const float* __restrict__ b4,
    const float* __restrict__ W5, const float* __restrict__ b5,
    const float* __restrict__ W6, const float* __restrict__ b6,
    float* __restrict__ out) {
    extern __shared__ float smem[];
    float* sB   = smem;               // 4096
    float* sZ   = smem + 4096;        // 4096
    float* sP   = smem + 8192;        // 4096
    float* sU   = smem + 12288;       // 4096
    float* sv   = smem + 16384;       // 256 small vectors
    float* sred = smem + 16384 + 256; // 32 reduction scratch

    const int n = blockIdx.x;
    const int t = threadIdx.x;
    const float* gi = g_gi + (size_t)n * GDIM;

    // ---- build B = I - (A^T - A), A lower-tri from gi ----
    for (int e = t; e < GDIM; e += 256) {
        int i = (int)((1.0f + sqrtf(1.0f + 8.0f * (float)e)) * 0.5f);
        while (i * (i - 1) / 2 > e) i--;
        while ((i + 1) * i / 2 <= e) i++;
        int j   = e - i * (i - 1) / 2;
        float v = gi[e];
        sB[i * 64 + j] = v;    // i > j
        sB[j * 64 + i] = -v;
    }
    if (t < 64) sB[t * 65] = 1.0f;
    __syncthreads();

    // ---- norms = sum(|B|) * max(|B|), Z0 = B^T / norms ----
    float lsum = 0.f, lmax = 0.f;
#pragma unroll
    for (int q = 0; q < 16; q++) {
        float v = fabsf(sB[t * 16 + q]);
        lsum += v;
        lmax = fmaxf(lmax, v);
    }
#pragma unroll
    for (int o = 16; o; o >>= 1) {
        lsum += __shfl_xor_sync(0xFFFFFFFFu, lsum, o);
        lmax = fmaxf(lmax, __shfl_xor_sync(0xFFFFFFFFu, lmax, o));
    }
    if ((t & 31) == 0) { sred[t >> 5] = lsum; sred[8 + (t >> 5)] = lmax; }
    __syncthreads();
    if (t == 0) {
        float S = 0.f, M = 0.f;
        for (int w = 0; w < 8; w++) { S += sred[w]; M = fmaxf(M, sred[8 + w]); }
        sred[16] = 1.0f / (S * M);
    }
    __syncthreads();
    const float invn = sred[16];
#pragma unroll
    for (int q = 0; q < 16; q++) {
        int e = t * 16 + q;
        int i = e >> 6, j = e & 63;
        sZ[e] = sB[j * 64 + i] * invn;
    }
    __syncthreads();

    // ---- 10 Newton-Schulz iterations ----
    // Z = 0.25 * Z @ (13I - BZ@(15I - BZ@(7I - BZ)))
#pragma unroll 1
    for (int it = 0; it < 10; it++) {
        mm_step(sB, sZ, sP, 0.0f, 1.0f);     // P  = B@Z
        mm_step(sP, sP, sU, 7.0f, -1.0f);    // U  = 7P - P@P        (= BZ@(7I-BZ))
        mm_step(sP, sU, sU, 15.0f, -1.0f);   // U  = 15P - P@U       (= BZ@(15I-...))
        mm_step(sZ, sU, sZ, 3.25f, -0.25f);  // Z  = 0.25*(13Z - Z@U)
    }
    // R = Z @ Q = Z @ (2I - B) = 2Z - Z@B   -> stored in sP
    mm_step(sZ, sB, sP, 2.0f, -1.0f);
    const float* R = sP;

    // ---- MLP tail ----
    if (t < 64) sv[t] = li_latent[n * 64 + t];
    __syncthreads();

    // mis[j] = sum_i R[i][j] * li[i]
    if (t < 64) {
        float acc = 0.f;
        for (int i = 0; i < 64; i++) acc += R[i * 64 + t] * sv[i];
        sv[64 + t] = acc;
    }
    __syncthreads();
    // h = relu(mis @ W1^T + b1)
    if (t < 64) {
        float acc = b1[t];
        const float* w = W1 + t * 64;
        for (int k = 0; k < 64; k++) acc += sv[64 + k] * w[k];
        sv[128 + t] = fmaxf(acc, 0.f);
    }
    __syncthreads();
    // fc2 = h @ W2^T + b2
    if (t < 64) {
        float acc = b2[t];
        const float* w = W2 + t * 64;
        for (int k = 0; k < 64; k++) acc += sv[128 + k] * w[k];
        sv[192 + t] = acc;
    }
    __syncthreads();
    // latent[i] = sum_j R[i][j] * fc2[j]   (skewed j to dodge bank conflicts)
    if (t < 64) {
        float acc = 0.f;
        for (int jj = 0; jj < 64; jj++) {
            int j = (t + jj) & 63;
            acc += R[t * 64 + j] * sv[192 + j];
        }
        sv[64 + t] = acc;                       // latent (overwrites mis)
        out[262144 + 8192 + n * 64 + t] = acc;  // latent output
    }
    __syncthreads();
    // t3 = relu(latent @ W3^T + b3)
    if (t < 64) {
        float acc = b3[t];
        const float* w = W3 + t * 64;
        for (int k = 0; k < 64; k++) acc += sv[64 + k] * w[k];
        sv[128 + t] = fmaxf(acc, 0.f);
    }
    __syncthreads();
    // recons = t3 @ W4^T + b4 ; t5 = relu(latent @ W5^T + b5)
    if (t < 64) {
        float acc = b4[t];
        const float* w = W4 + t * 64;
        for (int j = 0; j < 64; j++) acc += sv[128 + j] * w[j];
        out[n * 64 + t] = acc;                  // recons output

        float acc5 = b5[t];
        const float* w5 = W5 + t * 64;
        for (int k = 0; k < 64; k++) acc5 += sv[64 + k] * w5[k];
        sv[192 + t] = fmaxf(acc5, 0.f);         // t5 (overwrites fc2)
    }
    __syncthreads();
    // pred = t5 @ W6^T + b6   (2 outputs)
    if (t < 2) {
        float acc = b6[t];
        const float* w = W6 + t * 64;
        for (int j = 0; j < 64; j++) acc += sv[192 + j] * w[j];
        out[262144 + n * 2 + t] = acc;          // pred output
    }
}

// ---------------------------------------------------------------------------
// launch
// ---------------------------------------------------------------------------
#define MAIN_SMEM_BYTES ((4 * 4096 + 256 + 32) * sizeof(float))

extern "C" void kernel_launch(void* const* d_in, const int* in_sizes, int n_in,
                              void* d_out, int out_size) {
    const float* li    = (const float*)d_in[0];
    const float* gl    = (const float*)d_in[1];
    const float* W_up  = (const float*)d_in[2];
    const float* b_up  = (const float*)d_in[3];
    const float* W1    = (const float*)d_in[4];
    const float* b1    = (const float*)d_in[5];
    const float* W2    = (const float*)d_in[6];
    const float* b2    = (const float*)d_in[7];
    const float* W3    = (const float*)d_in[8];
    const float* b3    = (const float*)d_in[9];
    const float* W4    = (const float*)d_in[10];
    const float* b4    = (const float*)d_in[11];
    const float* W5    = (const float*)d_in[12];
    const float* b5    = (const float*)d_in[13];
    const float* W6    = (const float*)d_in[14];
    const float* b6    = (const float*)d_in[15];
    float* out = (float*)d_out;

    cudaFuncSetAttribute(k_main, cudaFuncAttributeMaxDynamicSharedMemorySize,
                         (int)MAIN_SMEM_BYTES);

    k_up<<<dim3((GDIM + 63) / 64, NB / 64), 256>>>(gl, W_up, b_up);
    k_main<<<NB, 256, MAIN_SMEM_BYTES>>>(li, W1, b1, W2, b2, W3, b3, W4, b4,
                                         W5, b5, W6, b6, out);
}